// round 6
// baseline (speedup 1.0000x reference)
#include <cuda_runtime.h>
#include <cstdint>
#include <cstddef>

// Ridge_51178830299316 — rank-2 RLS (Woodbury), 2D-tiled M, SCALAR FFMA (round 6).
//
// Model fitting rounds 1-5: packed fma.rn.f32x2 runs at reduced rate on this
// part (~rt4+/SMSP), pinning rounds 2/3/5 at ~1024 cyc/point; round 1 hit the
// same wall via LDS broadcast wavefronts. This round combines the low-LDS
// 4x8 tiling of round 5 (320 cyc/pt of LDS) with scalar FFMA (rt 2/SMSP ->
// 512 cyc/pt floor).
//
// Layout: P threads (0..511) each own a 4x8 tile of M:
//   rg = tid>>4 (rows 4rg..4rg+3), cg = tid&15 (cols 8cg..8cg+7)
// Per iteration (2 points): load au[4], bu[4] (row side) + pc[8], vc[8],
// x_{k+2}[8], x_{k+3}[8] (col side); apply previous block's rank-2 update
// fused with two matvecs (4 FFMA per element); reduce the 8 row-sums across
// the 16 lanes of each row-group via shfl.xor; lane cg==0 stores float4s.
// S warp (512..543): identical to the passing round-3/5 kernel — staleness
// correction in registers, one 10-value butterfly reduce, scalar Woodbury
// math, both predictions, w update. One __syncthreads per 2 points.

#define BATCH 32
#define NPTS  256
#define DIM   128
#define PTHREADS 512
#define TOT   544
#define NBLK  128            // blocks of 2 steps (x padded with 2 zero rows)

struct SMLayout {
    float xs[NPTS + 2][DIM];     // padded with 2 zero rows
    float ts[NPTS];
    float part[2][2][DIM];       // [buf][matvec 0/1][row] — fully reduced
    float pc[2][DIM];            // column-side p
    float vc[2][DIM];            // column-side v
    float au[2][DIM];            // inv1 * p  (row-side)
    float bu[2][DIM];            // inv2 * v  (row-side)
};

__global__ void __launch_bounds__(TOT, 1)
ridge_rls2s_kernel(const float* __restrict__ data,
                   const float* __restrict__ targets,
                   float* __restrict__ out)
{
    extern __shared__ char smem_raw[];
    SMLayout& sm = *reinterpret_cast<SMLayout*>(smem_raw);
    const int tid = threadIdx.x;
    const int b   = blockIdx.x;

    // ---- Stage inputs ----
    {
        const float4* src = reinterpret_cast<const float4*>(data + (size_t)b * NPTS * DIM);
        float4* dst = reinterpret_cast<float4*>(&sm.xs[0][0]);
        for (int idx = tid; idx < NPTS * DIM / 4; idx += TOT)
            dst[idx] = src[idx];
        if (tid < 2 * DIM / 4)
            reinterpret_cast<float4*>(&sm.xs[NPTS][0])[tid] =
                make_float4(0.f, 0.f, 0.f, 0.f);
        if (tid < NPTS / 4)
            reinterpret_cast<float4*>(sm.ts)[tid] =
                reinterpret_cast<const float4*>(targets + (size_t)b * NPTS)[tid];
    }
    __syncthreads();

    // ---- Prologue: raw matvecs of block 0 are I*x_0, I*x_1 ----
    if (tid < DIM) {
        sm.part[0][0][tid] = sm.xs[0][tid];
        sm.part[0][1][tid] = sm.xs[1][tid];
        sm.pc[0][tid] = 0.f;  sm.vc[0][tid] = 0.f;   // block -1 update = 0
        sm.au[0][tid] = 0.f;  sm.bu[0][tid] = 0.f;
    }
    if (tid == 0) out[(size_t)b * NPTS] = 0.f;
    __syncthreads();

    // ---- P persistent state: 4x8 tile of M = I, scalar registers ----
    const int rg = tid >> 4;      // row group: rows 4rg..4rg+3
    const int cg = tid & 15;      // col group: cols 8cg..8cg+7
    float mr[4][8];
    if (tid < PTHREADS) {
        #pragma unroll
        for (int r = 0; r < 4; r++)
            #pragma unroll
            for (int c = 0; c < 8; c++)
                mr[r][c] = (4 * rg + r == 8 * cg + c) ? 1.0f : 0.0f;
    }

    // ---- S persistent state (4 rows per lane) ----
    const int lane = tid - PTHREADS;
    const int i0   = lane * 4;
    float w0 = 0.f, w1 = 0.f, w2 = 0.f, w3 = 0.f;
    float pp0 = 0.f, pp1 = 0.f, pp2 = 0.f, pp3 = 0.f;
    float pv0 = 0.f, pv1 = 0.f, pv2 = 0.f, pv3 = 0.f;
    float cp0 = 0.f, cv0 = 0.f, cp1 = 0.f, cv1 = 0.f;

    int buf = 0;
    #pragma unroll 1
    for (int t = 0; t < NBLK; t++) {
        const int k = 2 * t;
        if (tid < PTHREADS) {
            // ===== P: rank-2 update (prev block) fused with 2 matvecs =====
            const float4 a1 = *reinterpret_cast<const float4*>(&sm.au[buf][rg * 4]);
            const float4 a2 = *reinterpret_cast<const float4*>(&sm.bu[buf][rg * 4]);
            const float A1[4] = { -a1.x, -a1.y, -a1.z, -a1.w };
            const float A2[4] = { -a2.x, -a2.y, -a2.z, -a2.w };

            float pcv[8], vcv[8], x0v[8], x1v[8];
            {
                const float4 t0 = reinterpret_cast<const float4*>(&sm.pc[buf][cg * 8])[0];
                const float4 t1 = reinterpret_cast<const float4*>(&sm.pc[buf][cg * 8])[1];
                pcv[0]=t0.x; pcv[1]=t0.y; pcv[2]=t0.z; pcv[3]=t0.w;
                pcv[4]=t1.x; pcv[5]=t1.y; pcv[6]=t1.z; pcv[7]=t1.w;
            }
            {
                const float4 t0 = reinterpret_cast<const float4*>(&sm.vc[buf][cg * 8])[0];
                const float4 t1 = reinterpret_cast<const float4*>(&sm.vc[buf][cg * 8])[1];
                vcv[0]=t0.x; vcv[1]=t0.y; vcv[2]=t0.z; vcv[3]=t0.w;
                vcv[4]=t1.x; vcv[5]=t1.y; vcv[6]=t1.z; vcv[7]=t1.w;
            }
            {
                const float4 t0 = reinterpret_cast<const float4*>(&sm.xs[k + 2][cg * 8])[0];
                const float4 t1 = reinterpret_cast<const float4*>(&sm.xs[k + 2][cg * 8])[1];
                x0v[0]=t0.x; x0v[1]=t0.y; x0v[2]=t0.z; x0v[3]=t0.w;
                x0v[4]=t1.x; x0v[5]=t1.y; x0v[6]=t1.z; x0v[7]=t1.w;
            }
            {
                const float4 t0 = reinterpret_cast<const float4*>(&sm.xs[k + 3][cg * 8])[0];
                const float4 t1 = reinterpret_cast<const float4*>(&sm.xs[k + 3][cg * 8])[1];
                x1v[0]=t0.x; x1v[1]=t0.y; x1v[2]=t0.z; x1v[3]=t0.w;
                x1v[4]=t1.x; x1v[5]=t1.y; x1v[6]=t1.z; x1v[7]=t1.w;
            }

            float acc0[4] = {0.f, 0.f, 0.f, 0.f};
            float acc1[4] = {0.f, 0.f, 0.f, 0.f};
            #pragma unroll
            for (int r = 0; r < 4; r++) {
                #pragma unroll
                for (int c = 0; c < 8; c++) {
                    float mv = mr[r][c];
                    mv = fmaf(A1[r], pcv[c], mv);
                    mv = fmaf(A2[r], vcv[c], mv);
                    mr[r][c] = mv;
                    acc0[r] = fmaf(mv, x0v[c], acc0[r]);
                    acc1[r] = fmaf(mv, x1v[c], acc1[r]);
                }
            }
            // reduce across the 16 lanes sharing this row group
            #pragma unroll
            for (int off = 1; off < 16; off <<= 1) {
                #pragma unroll
                for (int r = 0; r < 4; r++) {
                    acc0[r] += __shfl_xor_sync(0xffffffffu, acc0[r], off);
                    acc1[r] += __shfl_xor_sync(0xffffffffu, acc1[r], off);
                }
            }
            if (cg == 0) {
                *reinterpret_cast<float4*>(&sm.part[buf ^ 1][0][rg * 4]) =
                    make_float4(acc0[0], acc0[1], acc0[2], acc0[3]);
                *reinterpret_cast<float4*>(&sm.part[buf ^ 1][1][rg * 4]) =
                    make_float4(acc1[0], acc1[1], acc1[2], acc1[3]);
            }
        } else {
            // ===== S: correct staleness, 10-value reduce, scalar math =====
            const float4 pr = *reinterpret_cast<const float4*>(&sm.part[buf][0][i0]);
            const float4 qr = *reinterpret_cast<const float4*>(&sm.part[buf][1][i0]);
            const float p0 = pr.x - cp0 * pp0 - cv0 * pv0;
            const float p1 = pr.y - cp0 * pp1 - cv0 * pv1;
            const float p2 = pr.z - cp0 * pp2 - cv0 * pv2;
            const float p3 = pr.w - cp0 * pp3 - cv0 * pv3;
            const float q0 = qr.x - cp1 * pp0 - cv1 * pv0;
            const float q1 = qr.y - cp1 * pp1 - cv1 * pv1;
            const float q2 = qr.z - cp1 * pp2 - cv1 * pv2;
            const float q3 = qr.w - cp1 * pp3 - cv1 * pv3;

            const float4 xk  = *reinterpret_cast<const float4*>(&sm.xs[k][i0]);
            const float4 xk1 = *reinterpret_cast<const float4*>(&sm.xs[k + 1][i0]);
            const float4 xk2 = *reinterpret_cast<const float4*>(&sm.xs[k + 2][i0]);
            const float4 xk3 = *reinterpret_cast<const float4*>(&sm.xs[k + 3][i0]);

            float s1v = (xk.x  * p0 + xk.y  * p1) + (xk.z  * p2 + xk.w  * p3);
            float cS  = (xk.x  * q0 + xk.y  * q1) + (xk.z  * q2 + xk.w  * q3);
            float s2  = (xk1.x * q0 + xk1.y * q1) + (xk1.z * q2 + xk1.w * q3);
            float ew0 = (xk.x  * w0 + xk.y  * w1) + (xk.z  * w2 + xk.w  * w3);
            float ew1 = (xk1.x * w0 + xk1.y * w1) + (xk1.z * w2 + xk1.w * w3);
            float ew2 = (xk2.x * w0 + xk2.y * w1) + (xk2.z * w2 + xk2.w * w3);
            float d1  = (xk2.x * p0 + xk2.y * p1) + (xk2.z * p2 + xk2.w * p3);
            float d2  = (xk2.x * q0 + xk2.y * q1) + (xk2.z * q2 + xk2.w * q3);
            float d3  = (xk3.x * p0 + xk3.y * p1) + (xk3.z * p2 + xk3.w * p3);
            float d4  = (xk3.x * q0 + xk3.y * q1) + (xk3.z * q2 + xk3.w * q3);

            #pragma unroll
            for (int off = 16; off > 0; off >>= 1) {
                s1v += __shfl_xor_sync(0xffffffffu, s1v, off);
                cS  += __shfl_xor_sync(0xffffffffu, cS,  off);
                s2  += __shfl_xor_sync(0xffffffffu, s2,  off);
                ew0 += __shfl_xor_sync(0xffffffffu, ew0, off);
                ew1 += __shfl_xor_sync(0xffffffffu, ew1, off);
                ew2 += __shfl_xor_sync(0xffffffffu, ew2, off);
                d1  += __shfl_xor_sync(0xffffffffu, d1,  off);
                d2  += __shfl_xor_sync(0xffffffffu, d2,  off);
                d3  += __shfl_xor_sync(0xffffffffu, d3,  off);
                d4  += __shfl_xor_sync(0xffffffffu, d4,  off);
            }

            const float inv1  = 1.0f / (1.0f + s1v);
            const float coef0 = (sm.ts[k] - ew0) * inv1;
            const float cc    = cS * inv1;
            const float t2    = s2 - cS * cc;
            const float inv2  = 1.0f / (1.0f + t2);
            const float pred1 = fmaf(coef0, cS, ew1);
            const float coef1 = (sm.ts[k + 1] - pred1) * inv2;
            const float pred2 = ew2 + coef0 * d1 + coef1 * (d2 - cc * d1);

            const float nv0 = q0 - cc * p0, nv1 = q1 - cc * p1;
            const float nv2 = q2 - cc * p2, nv3 = q3 - cc * p3;
            w0 += coef0 * p0 + coef1 * nv0;
            w1 += coef0 * p1 + coef1 * nv1;
            w2 += coef0 * p2 + coef1 * nv2;
            w3 += coef0 * p3 + coef1 * nv3;

            const int nb = buf ^ 1;
            *reinterpret_cast<float4*>(&sm.pc[nb][i0]) = make_float4(p0, p1, p2, p3);
            *reinterpret_cast<float4*>(&sm.vc[nb][i0]) = make_float4(nv0, nv1, nv2, nv3);
            *reinterpret_cast<float4*>(&sm.au[nb][i0]) =
                make_float4(inv1 * p0, inv1 * p1, inv1 * p2, inv1 * p3);
            *reinterpret_cast<float4*>(&sm.bu[nb][i0]) =
                make_float4(inv2 * nv0, inv2 * nv1, inv2 * nv2, inv2 * nv3);

            if (lane == 0) {
                out[(size_t)b * NPTS + k + 1] = pred1;
                if (k + 2 < NPTS) out[(size_t)b * NPTS + k + 2] = pred2;
            }

            pp0 = p0; pp1 = p1; pp2 = p2; pp3 = p3;
            pv0 = nv0; pv1 = nv1; pv2 = nv2; pv3 = nv3;
            cp0 = inv1 * d1;  cv0 = inv2 * (d2 - cc * d1);
            cp1 = inv1 * d3;  cv1 = inv2 * (d4 - cc * d3);
        }
        __syncthreads();
        buf ^= 1;
    }
}

extern "C" void kernel_launch(void* const* d_in, const int* in_sizes, int n_in,
                              void* d_out, int out_size)
{
    const float* data    = (const float*)d_in[0];   // [32, 256, 128] f32
    const float* targets = (const float*)d_in[1];   // [32, 256]      f32
    float* out = (float*)d_out;                     // [32, 256]      f32

    const size_t smem_bytes = sizeof(SMLayout);
    cudaFuncSetAttribute(ridge_rls2s_kernel,
                         cudaFuncAttributeMaxDynamicSharedMemorySize,
                         (int)smem_bytes);
    ridge_rls2s_kernel<<<BATCH, TOT, smem_bytes>>>(data, targets, out);
}